// round 17
// baseline (speedup 1.0000x reference)
#include <cuda_runtime.h>
#include <cstdint>

// Spatial correlation sampler: out[b][dy][dx][y][x] =
//   sum_c in1[b,c,y,x] * in2[b,c,y+dy-4,x+dx-4]   (zero padded), dy,dx in 0..8
//
// Round-17: px4 consumers under the r13/r16 mbarrier pipeline.
//   block = full 128-px row tile; 9 consumer warps (ri,g in 3x3; lane = 4 px)
//   + 1 producer warp. 27 (dy,dx) accumulators as 2 f32x2 pairs = 108 regs.
//   CHPS=8, 3 slots (174 KB dyn smem), dead-warp skip, 1 block/SM.
//   Per channel per SM: crossbar 216 cyc (was 288), LDS instrs / 2.7.

#define CC 128
#define HH 96
#define WW 128
#define HW (HH * WW)

#define NTHR    320            // warps 0..8 consume, warp 9 produces
#define NCW     9
#define CHPS    8              // channels per stage
#define STAGES  (CC / CHPS)    // 16
#define NBUF    3
#define W2      136            // in2 smem row: 4 + 128 + 4 floats
#define W1      128            // in1 smem row floats
#define CHF     (3 * W2 + 11 * W1)   // 1816 floats per channel slab
#define CHFB    (CHF * 4)            // 7264 B
#define BUFF    (CHPS * CHF)         // floats per slot
#define BUFB    (BUFF * 4)           // 58112 B per slot
#define SMEMB   (NBUF * BUFB)        // 174336 B

typedef unsigned long long ull;

__device__ __forceinline__ void fma2(ull& acc, ull a, ull b) {
    asm("fma.rn.f32x2 %0, %1, %2, %0;" : "+l"(acc) : "l"(a), "l"(b));
}

__device__ __forceinline__ ull pkmid(ull a, ull b) {
    ull r;
    asm("{ .reg .b32 al, ah, bl, bh;\n\t"
        "  mov.b64 {al, ah}, %1;\n\t"
        "  mov.b64 {bl, bh}, %2;\n\t"
        "  mov.b64 %0, {ah, bl}; }"
        : "=l"(r) : "l"(a), "l"(b));
    return r;
}

__device__ __forceinline__ float2 unpk(ull v) {
    unsigned lo, hi;
    asm("mov.b64 {%0,%1}, %2;" : "=r"(lo), "=r"(hi) : "l"(v));
    return make_float2(__uint_as_float(lo), __uint_as_float(hi));
}

__device__ __forceinline__ void cp16(uint32_t dst, const float* src) {
    asm volatile("cp.async.cg.shared.global [%0], [%1], 16;"
                 :: "r"(dst), "l"(src) : "memory");
}

__device__ __forceinline__ void mbar_init(uint32_t a, uint32_t cnt) {
    asm volatile("mbarrier.init.shared.b64 [%0], %1;" :: "r"(a), "r"(cnt)
                 : "memory");
}
__device__ __forceinline__ void mbar_arrive(uint32_t a) {
    asm volatile("mbarrier.arrive.release.cta.shared::cta.b64 _, [%0];"
                 :: "r"(a) : "memory");
}
__device__ __forceinline__ void cp_arrive_noinc(uint32_t a) {
    asm volatile("cp.async.mbarrier.arrive.noinc.shared::cta.b64 [%0];"
                 :: "r"(a) : "memory");
}
__device__ __forceinline__ void mbar_wait(uint32_t a, uint32_t ph) {
    uint32_t done;
    do {
        asm volatile(
            "{ .reg .pred p;\n\t"
            "mbarrier.try_wait.parity.acquire.cta.shared::cta.b64 p, [%1], %2, 0x989680;\n\t"
            "selp.b32 %0, 1, 0, p; }"
            : "=r"(done) : "r"(a), "r"(ph) : "memory");
    } while (!done);
}

__device__ __forceinline__ int clampi(int v, int lo, int hi) {
    return v < lo ? lo : (v > hi ? hi : v);
}

__global__ __launch_bounds__(NTHR, 1) void corr_kernel(
    const float* __restrict__ in1,
    const float* __restrict__ in2,
    float* __restrict__ out)
{
    // slab layout (floats): [0, 3*136)   = 3 in2 rows, 4-float pads both ends
    //                       [408, 1816)  = 11 in1 rows x 128
    extern __shared__ float sm[];
    __shared__ ull mbar[2 * NBUF];       // [0..2]=full, [3..5]=empty

    const int tid  = threadIdx.x;
    const int lane = tid & 31;
    const int w    = tid >> 5;            // 0..9
    const int b    = blockIdx.y;
    const int r0   = blockIdx.x * 3 - 4;

    const float* p1base = in1 + (size_t)b * CC * HW;
    const float* p2base = in2 + (size_t)b * CC * HW;
    const uint32_t smb  = (uint32_t)__cvta_generic_to_shared(sm);
    const uint32_t mbb  = (uint32_t)__cvta_generic_to_shared(mbar);

    // ---- init mbarriers + zero in2 pad columns ----
    if (tid < NBUF) {
        mbar_init(mbb + tid * 8, 32);                // full: 32 producer lanes
        mbar_init(mbb + (NBUF + tid) * 8, NCW * 32); // empty: 288 consumers
    }
    // pads: 3 bufs x 8 ch x 3 rows x 8 floats = 576
    for (int i = tid; i < 576; i += NTHR) {
        const int bu = i / 192, q = i % 192;
        const int ch = q / 24, q2 = q % 24;
        const int rr = q2 / 8, k = q2 & 7;
        sm[(size_t)bu * BUFF + ch * CHF + rr * W2 + (k < 4 ? k : 128 + k)] = 0.0f;
    }
    __syncthreads();   // once; main loop is barrier-free

    if (w == NCW) {
        // ================= PRODUCER WARP =================
        // 448 chunks per channel: 96 in2 (3 rows x 32) + 352 in1 (11 x 32);
        // 448/32 = 14 chunks per lane, uniform.
        const float* srcp[14];
        uint32_t     dstb[14];        // byte offset within a channel slab
        #pragma unroll
        for (int j = 0; j < 14; j++) {
            const int n = lane + 32 * j;
            if (n < 96) {
                const int rr = n >> 5, k = n & 31;
                const int srow = clampi(r0 + rr, 0, HH - 1);
                srcp[j] = p2base + (size_t)srow * WW + 4 * k;
                dstb[j] = (uint32_t)((rr * W2 + 4 + 4 * k) << 2);
            } else {
                const int m = n - 96;
                const int rw = m >> 5, k = m & 31;
                const int srow = clampi(r0 - 4 + rw, 0, HH - 1);
                srcp[j] = p1base + (size_t)srow * WW + 4 * k;
                dstb[j] = (uint32_t)((408 + rw * W1 + 4 * k) << 2);
            }
        }

        #pragma unroll 1
        for (int s = 0; s < STAGES; s++) {
            const int slot = s % NBUF;
            const int use  = s / NBUF;
            if (use > 0)
                mbar_wait(mbb + (NBUF + slot) * 8, (use - 1) & 1);

            const uint32_t bo = smb + slot * BUFB;
            #pragma unroll 2
            for (int ch = 0; ch < CHPS; ch++) {
                const size_t co = (size_t)(CHPS * s + ch) * HW;
                const uint32_t bc = bo + ch * CHFB;
                #pragma unroll
                for (int j = 0; j < 14; j++)
                    cp16(bc + dstb[j], srcp[j] + co);
            }
            cp_arrive_noinc(mbb + slot * 8);   // deferred, counts vs init=32
        }
    } else {
        // ================= CONSUMER WARPS =================
        const int g  = w % 3;            // dy group: dy = 3g..3g+2
        const int ri = w / 3;            // in2 row of the tile
        const int r  = r0 + ri;
        const int x0 = 4 * lane;         // 4 pixels x0..x0+3
        const bool alive = (r >= 0 && r < HH);   // warp-uniform

        const int jbase = ri + 8 - 3 * g;              // 2..10
        const int winf  = ri * W2 + x0;                // window floats x0..x0+11
        const int af0   = 408 + jbase * W1 + x0;       // A row t=0; t -> -W1

        ull acc[3][9][2];
        #pragma unroll
        for (int t = 0; t < 3; t++)
            #pragma unroll
            for (int d = 0; d < 9; d++) {
                acc[t][d][0] = 0ull;
                acc[t][d][1] = 0ull;
            }

        #pragma unroll 1
        for (int s = 0; s < STAGES; s++) {
            const int slot = s % NBUF;
            mbar_wait(mbb + slot * 8, (s / NBUF) & 1);

            if (alive) {   // dead warps only pace the protocol
                const float* bufbase = sm + slot * BUFF;
                #pragma unroll
                for (int u = 0; u < CHPS; u++) {
                    const float* base = bufbase + u * CHF;
                    const ulonglong2* q = (const ulonglong2*)(base + winf);
                    const ulonglong2 Lv = q[0], Mv = q[1], Rv = q[2];
                    const float* ab = base + af0;
                    const ulonglong2 A0 = *(const ulonglong2*)(ab);
                    const ulonglong2 A1 = *(const ulonglong2*)(ab - W1);
                    const ulonglong2 A2 = *(const ulonglong2*)(ab - 2 * W1);

                    ull wp[11];
                    wp[0] = Lv.x;  wp[2] = Lv.y;  wp[4]  = Mv.x;
                    wp[6] = Mv.y;  wp[8] = Rv.x;  wp[10] = Rv.y;
                    wp[1] = pkmid(Lv.x, Lv.y);
                    wp[3] = pkmid(Lv.y, Mv.x);
                    wp[5] = pkmid(Mv.x, Mv.y);
                    wp[7] = pkmid(Mv.y, Rv.x);
                    wp[9] = pkmid(Rv.x, Rv.y);

                    #pragma unroll
                    for (int d = 0; d < 9; d++) {
                        fma2(acc[0][d][0], A0.x, wp[d]);
                        fma2(acc[0][d][1], A0.y, wp[d + 2]);
                        fma2(acc[1][d][0], A1.x, wp[d]);
                        fma2(acc[1][d][1], A1.y, wp[d + 2]);
                        fma2(acc[2][d][0], A2.x, wp[d]);
                        fma2(acc[2][d][1], A2.y, wp[d + 2]);
                    }
                }
            }
            mbar_arrive(mbb + (NBUF + slot) * 8);   // release the slot
        }

        // ---- epilogue (dead warps write exact-zero outputs) ----
        #pragma unroll
        for (int t = 0; t < 3; t++) {
            const int y = r + 4 - (3 * g + t);
            if (y < 0 || y >= HH) continue;        // warp-uniform
            const int dy = 3 * g + t;
            #pragma unroll
            for (int d = 0; d < 9; d++) {
                const float2 lo = unpk(acc[t][d][0]);
                const float2 hi = unpk(acc[t][d][1]);
                float* po = out + (((((size_t)b * 9 + dy) * 9 + d) * HH + y) * WW) + x0;
                *(float4*)po = make_float4(lo.x, lo.y, hi.x, hi.y);
            }
        }
    }
}

extern "C" void kernel_launch(void* const* d_in, const int* in_sizes, int n_in,
                              void* d_out, int out_size)
{
    const float* in1 = (const float*)d_in[0];
    const float* in2 = (const float*)d_in[1];
    float* out = (float*)d_out;

    cudaFuncSetAttribute(corr_kernel,
                         cudaFuncAttributeMaxDynamicSharedMemorySize, SMEMB);

    // x = r-tile (35 tiles cover r=-4..100), y = batch
    dim3 grid(35, 8, 1);
    corr_kernel<<<grid, NTHR, SMEMB>>>(in1, in2, out);
}